// round 15
// baseline (speedup 1.0000x reference)
#include <cuda_runtime.h>
#include <cuda_bf16.h>
#include <cuda_fp16.h>
#include <math.h>
#include <stdint.h>

// Problem constants
#define B_  2
#define T_  2048
#define D_  2048
#define NH  16
#define NKV 4
#define HD  128
#define M_  (B_ * T_)          // 4096
#define KVD (NKV * HD)         // 512
#define ROPE_THETA 1000000.0

typedef unsigned long long ull;

// ---------------------------------------------------------------------------
// Scratch (device globals; no allocation allowed)
// ---------------------------------------------------------------------------
__device__ float g_q[M_ * NH * HD];     // 32 MB
__device__ float g_k[M_ * KVD];         //  8 MB
__device__ float g_v[M_ * KVD];         //  8 MB
__device__ float g_cos[T_ * HD];
__device__ float g_sin[T_ * HD];

// fp16 GEMM operands.
__device__ __half g_xh[M_ * D_];                      // x     [M][K]
__device__ __half g_ah[M_ * D_];                      // attn  [M][K] (flash writes)
__device__ __half g_wqh[D_ * D_],  g_wql[D_ * D_];    // wq^T
__device__ __half g_woh[D_ * D_],  g_wol[D_ * D_];    // wo^T
__device__ __half g_wkh[KVD * D_], g_wkl[KVD * D_];   // wk^T
__device__ __half g_wvh[KVD * D_], g_wvl[KVD * D_];   // wv^T

// ---------------------------------------------------------------------------
// helpers
// ---------------------------------------------------------------------------
__device__ __forceinline__ unsigned pack_h2(float a, float b) {
    __half ha = __float2half_rn(a), hb = __float2half_rn(b);
    return (unsigned)__half_as_ushort(ha) |
           ((unsigned)__half_as_ushort(hb) << 16);
}

__device__ __forceinline__ void cp16(uint32_t dst, const void* src) {
    asm volatile("cp.async.cg.shared.global [%0], [%1], 16;\n"
                 :: "r"(dst), "l"(src));
}
#define CP_COMMIT() asm volatile("cp.async.commit_group;\n" ::: "memory")
#define CP_WAIT0()  asm volatile("cp.async.wait_group 0;\n" ::: "memory")

// packed fp32x2 ops (Blackwell f32x2 pipe; IEEE-identical per lane)
#define FMA_X2(d, a, b) \
    asm("fma.rn.f32x2 %0, %1, %2, %0;" : "+l"(d) : "l"(a), "l"(b))
#define MUL_X2(d, a) \
    asm("mul.rn.f32x2 %0, %0, %1;" : "+l"(d) : "l"(a))
#define PACK_X2(d, lo, hi) \
    asm("mov.b64 %0, {%1, %2};" : "=l"(d) : "f"(lo), "f"(hi))
#define UNPACK_X2(lo, hi, d) \
    asm("mov.b64 {%0, %1}, %2;" : "=f"(lo), "=f"(hi) : "l"(d))

// ldmatrix: 4x m8n8 b16 tiles
#define LDSM_X4(r0, r1, r2, r3, addr)                                        \
    asm volatile("ldmatrix.sync.aligned.m8n8.x4.shared.b16 "                 \
                 "{%0,%1,%2,%3}, [%4];"                                      \
                 : "=r"(r0), "=r"(r1), "=r"(r2), "=r"(r3) : "r"(addr))

// ---------------------------------------------------------------------------
// RoPE cache (double precision angles; t*inv_freq reaches ~2047 rad)
// ---------------------------------------------------------------------------
__global__ void rope_cache_kernel() {
    int t = blockIdx.x;
    int d = threadIdx.x;            // 0..127
    int d2 = d & 63;
    double inv_freq = exp(-((double)(2 * d2) / (double)HD) * log(ROPE_THETA));
    double ang = (double)t * inv_freq;
    g_cos[t * HD + d] = (float)cos(ang);
    g_sin[t * HD + d] = (float)sin(ang);
}

// ---------------------------------------------------------------------------
// RoPE apply (in place): buf layout [B*T, nh, 128]
// ---------------------------------------------------------------------------
__global__ void rope_apply_kernel(float* __restrict__ buf, int nh) {
    int idx = blockIdx.x * blockDim.x + threadIdx.x;
    int total = M_ * nh * 64;
    if (idx >= total) return;
    int d2 = idx & 63;
    int h  = (idx >> 6) % nh;
    int bt = idx / (64 * nh);
    int t  = bt % T_;
    int base = (bt * nh + h) * HD;
    float a = buf[base + d2];
    float b = buf[base + d2 + 64];
    float c = g_cos[t * HD + d2];
    float s = g_sin[t * HD + d2];
    buf[base + d2]      = a * c - b * s;
    buf[base + d2 + 64] = b * c + a * s;
}

// ---------------------------------------------------------------------------
// Conversions.
// ---------------------------------------------------------------------------
__global__ void cvt_h_kernel(const float* __restrict__ in,
                             __half* __restrict__ out, int n4) {
    int i = blockIdx.x * blockDim.x + threadIdx.x;
    if (i >= n4) return;
    float4 v = reinterpret_cast<const float4*>(in)[i];
    uint2 H;
    H.x = pack_h2(v.x, v.y);
    H.y = pack_h2(v.z, v.w);
    reinterpret_cast<uint2*>(out)[i] = H;
}

__global__ void cvt_splitT_kernel(const float* __restrict__ in,
                                  __half* __restrict__ hiT,
                                  __half* __restrict__ loT,
                                  int K, int N) {
    __shared__ float tile[32][33];
    int n0 = blockIdx.x * 32, k0 = blockIdx.y * 32;
    int tx = threadIdx.x, ty = threadIdx.y;     // (32, 8)
    #pragma unroll
    for (int i = 0; i < 4; i++)
        tile[ty + 8 * i][tx] = in[(size_t)(k0 + ty + 8 * i) * N + n0 + tx];
    __syncthreads();
    #pragma unroll
    for (int i = 0; i < 4; i++) {
        float v = tile[tx][ty + 8 * i];         // = in[k0+tx][n0+ty+8i]
        __half hb = __float2half_rn(v);
        size_t o = (size_t)(n0 + ty + 8 * i) * K + k0 + tx;
        hiT[o] = hb;
        loT[o] = __float2half_rn(v - __half2float(hb));
    }
}

// ---------------------------------------------------------------------------
// fp16 2-pass tensor-core GEMM:
//   C[M][N] fp32 = Ah[M][K] * (Bh + Bl)^T[N][K]
// Fragment loads via ldmatrix.x4 (8 LDSM per k16-slice instead of 32 LDS.32).
// 80B smem row stride -> ldmatrix phases hit banks {0,20,8,28,16,4,24,12}:
// conflict-free.
// ---------------------------------------------------------------------------
#define TBM 128
#define TBN 128
#define TBK 32
#define SROW 40
#define TILE_HF (TBM * SROW)
#define TILE_BYTES (TILE_HF * 2)
#define GEMM_SMEM (2 * 3 * TILE_BYTES)   // 61440 bytes

#define MMA_F16(c, a, b)                                                     \
    asm volatile("mma.sync.aligned.m16n8k16.row.col.f32.f16.f16.f32 "        \
                 "{%0,%1,%2,%3},{%4,%5,%6,%7},{%8,%9},{%0,%1,%2,%3};\n"      \
                 : "+f"((c)[0]), "+f"((c)[1]), "+f"((c)[2]), "+f"((c)[3])    \
                 : "r"((a)[0]), "r"((a)[1]), "r"((a)[2]), "r"((a)[3]),       \
                   "r"((b)[0]), "r"((b)[1]))

__global__ void __launch_bounds__(256, 2)
fgemm2_kernel(const __half* __restrict__ Ah,
              const __half* __restrict__ BhT,
              const __half* __restrict__ BlT,
              float* __restrict__ C, int Ndim, int Kdim) {
    extern __shared__ __half sm[];   // [2 bufs][3 mats][TILE_HF]
    const int tid  = threadIdx.x;
    const int lane = tid & 31;
    const int warp = tid >> 5;
    const int wm = (warp >> 2) * 64;
    const int wn = (warp & 3) * 32;
    const int bm = blockIdx.y * TBM;
    const int bn = blockIdx.x * TBN;

    const uint32_t sbase = (uint32_t)__cvta_generic_to_shared(sm);

    float acc[4][4][4];
    #pragma unroll
    for (int mi = 0; mi < 4; mi++)
        #pragma unroll
        for (int ni = 0; ni < 4; ni++)
            #pragma unroll
            for (int t = 0; t < 4; t++) acc[mi][ni][t] = 0.0f;

    const __half* gsrc[3] = {
        Ah  + (size_t)bm * Kdim,
        BhT + (size_t)bn * Kdim,
        BlT + (size_t)bn * Kdim
    };

    auto stage = [&](int bufi, int kt) {
        uint32_t sb = sbase + (uint32_t)bufi * (3 * TILE_BYTES);
        #pragma unroll
        for (int i = 0; i < 6; i++) {
            int idx = tid + 256 * i;
            int mat = idx >> 9;
            int j   = idx & 511;
            int row = j >> 2;
            int g   = j & 3;
            uint32_t dst = sb + (uint32_t)mat * TILE_BYTES
                         + (uint32_t)row * (SROW * 2) + (uint32_t)g * 16;
            cp16(dst, gsrc[mat] + (size_t)row * Kdim + kt + g * 8);
        }
    };

    // ldmatrix lane->address components (constant across k-loop)
    const int a_row = wm + (lane & 15);             // + mi*16
    const int a_col = (lane >> 4) << 3;             // + kk
    const int b_row = wn + (lane & 7) + ((lane >> 4) << 3);   // + ni*8
    const int b_col = ((lane >> 3) & 1) << 3;       // + kk

    auto compute = [&](int bufi) {
        const uint32_t sA  = sbase + (uint32_t)bufi * (3 * TILE_BYTES);
        const uint32_t sBh = sA + TILE_BYTES;
        const uint32_t sBl = sBh + TILE_BYTES;
        #pragma unroll
        for (int kk = 0; kk < TBK; kk += 16) {
            uint32_t a[4][4], bh[4][2], bl[4][2];
            #pragma unroll
            for (int mi = 0; mi < 4; mi++)
                LDSM_X4(a[mi][0], a[mi][1], a[mi][2], a[mi][3],
                        sA + (uint32_t)((a_row + mi * 16) * SROW
                                        + a_col + kk) * 2);
            #pragma unroll
            for (int np = 0; np < 2; np++) {
                int ni = np * 2;
                LDSM_X4(bh[ni][0], bh[ni][1], bh[ni + 1][0], bh[ni + 1][1],
                        sBh + (uint32_t)((b_row + ni * 8) * SROW
                                         + b_col + kk) * 2);
                LDSM_X4(bl[ni][0], bl[ni][1], bl[ni + 1][0], bl[ni + 1][1],
                        sBl + (uint32_t)((b_row + ni * 8) * SROW
                                         + b_col + kk) * 2);
            }
            #pragma unroll
            for (int mi = 0; mi < 4; mi++)
                #pragma unroll
                for (int ni = 0; ni < 4; ni++) {
                    MMA_F16(acc[mi][ni], a[mi], bh[ni]);
                    MMA_F16(acc[mi][ni], a[mi], bl[ni]);
                }
        }
    };

    const int ntiles = Kdim / TBK;
    stage(0, 0);
    CP_COMMIT();
    CP_WAIT0();
    __syncthreads();

    for (int it = 0; it < ntiles; ++it) {
        int cur = it & 1;
        if (it + 1 < ntiles) {
            stage(cur ^ 1, (it + 1) * TBK);
            CP_COMMIT();
        }
        compute(cur);
        CP_WAIT0();
        __syncthreads();
    }

    #pragma unroll
    for (int mi = 0; mi < 4; mi++) {
        int row = bm + wm + mi * 16 + (lane >> 2);
        #pragma unroll
        for (int ni = 0; ni < 4; ni++) {
            int col = bn + wn + ni * 8 + (lane & 3) * 2;
            *(float2*)&C[(size_t)row * Ndim + col] =
                make_float2(acc[mi][ni][0], acc[mi][ni][1]);
            *(float2*)&C[(size_t)(row + 8) * Ndim + col] =
                make_float2(acc[mi][ni][2], acc[mi][ni][3]);
        }
    }
}

// ---------------------------------------------------------------------------
// Causal GQA flash attention, 8 query rows per warp, packed f32x2 math.
// Block = 512 threads = 16 warps = 4 q-heads x 4 warps x 8 rows.
// QK dots: dim-paired f32x2 FMA. PV: row-paired f32x2 FMA with P stored as
// packed row-pairs in smem. Numerics identical to scalar fp32 (IEEE per lane).
// ---------------------------------------------------------------------------
#define FA_BN 32
#define KPAD 132
#define KV_TILE (FA_BN * KPAD)                         // 4224 floats
#define FA_QROWS 32
#define FLASH_SMEM ((2 * 2 * KV_TILE + 128 * HD + 16 * FA_BN * 8) * 4) // 149504

__global__ __launch_bounds__(512, 1)
void flash_attn_kernel() {
    extern __shared__ float fsm[];
    float* Qs = fsm + 2 * 2 * KV_TILE;      // [128 (head,row) vecs][HD]
    ull*   Pd = (ull*)(Qs + 128 * HD);      // [16 warps][32 keys][4 row-pairs]
    const uint32_t sbase = (uint32_t)__cvta_generic_to_shared(fsm);

    const int tid  = threadIdx.x;
    const int warp = tid >> 5;              // 0..15
    const int lane = tid & 31;
    const int b   = blockIdx.y / NKV;
    const int kvh = blockIdx.y % NKV;
    const int hg  = warp >> 2;
    const int h   = kvh * 4 + hg;
    const int r0  = blockIdx.x * FA_QROWS + (warp & 3) * 8;
    const int qbase = hg * 32 + (warp & 3) * 8;

    const float scale = 0.08838834764831845f;  // 1/sqrt(128)

    // stage Q: 128 vecs x 32 float4 groups = 4096 float4; 8 per thread
    #pragma unroll
    for (int i = 0; i < 8; i++) {
        int idx = tid + 512 * i;
        int qi = idx >> 5, g = idx & 31;
        int hq = qi >> 5, lr = qi & 31;
        *(float4*)&Qs[qi * HD + 4 * g] = *(const float4*)
            &g_q[((size_t)(b * T_ + blockIdx.x * FA_QROWS + lr) * NH
                  + kvh * 4 + hq) * HD + 4 * g];
    }

    auto stage_kv = [&](int bufi, int t0) {
        #pragma unroll
        for (int i = 0; i < 2; i++) {
            int idx = tid + 512 * i;
            int jj = idx >> 5, g = idx & 31;
            size_t gb = ((size_t)(b * T_ + t0 + jj) * NKV + kvh) * HD + 4 * g;
            uint32_t kdst = sbase +
                (uint32_t)(bufi * (2 * KV_TILE) + jj * KPAD + 4 * g) * 4u;
            cp16(kdst, &g_k[gb]);
            cp16(kdst + (uint32_t)KV_TILE * 4u, &g_v[gb]);
        }
    };

    stage_kv(0, 0);
    CP_COMMIT();
    CP_WAIT0();
    __syncthreads();

    float m[8], l[8];
    ull o2[4][4];                           // [row-pair][dim]: (o[2p][d],o[2p+1][d])
    #pragma unroll
    for (int rr = 0; rr < 8; rr++) { m[rr] = -INFINITY; l[rr] = 0.0f; }
    #pragma unroll
    for (int p = 0; p < 4; p++)
        #pragma unroll
        for (int d = 0; d < 4; d++) o2[p][d] = 0ull;

    const int ntiles = blockIdx.x + 1;
    for (int it = 0; it < ntiles; ++it) {
        int t0  = it * FA_BN;
        int cur = it & 1;
        if (it + 1 < ntiles) {
            stage_kv(cur ^ 1, t0 + FA_BN);
            CP_COMMIT();
        }
        const float* Kst = fsm + cur * (2 * KV_TILE);
        const float* Vst = Kst + KV_TILE;

        // phase 1: lane j scores key t0+j against all 8 rows (f32x2 pairs)
        ull a2[8];
        #pragma unroll
        for (int rr = 0; rr < 8; rr++) a2[rr] = 0ull;
        #pragma unroll 4
        for (int g = 0; g < 32; g++) {
            ulonglong2 k2 = *(const ulonglong2*)&Kst[lane * KPAD + 4 * g];
            #pragma unroll
            for (int rr = 0; rr < 8; rr++) {
                ulonglong2 q2 =
                    *(const ulonglong2*)&Qs[(qbase + rr) * HD + 4 * g];
                FMA_X2(a2[rr], q2.x, k2.x);
                FMA_X2(a2[rr], q2.y, k2.y);
            }
        }

        // phase 2: per-row streaming softmax bookkeeping
        float pv[8], corr[8];
        #pragma unroll
        for (int rr = 0; rr < 8; rr++) {
            float alo, ahi;
            UNPACK_X2(alo, ahi, a2[rr]);
            float av = alo + ahi;
            float s = (t0 + lane <= r0 + rr) ? av * scale : -INFINITY;
            float tmax = s;
            #pragma unroll
            for (int off = 16; off; off >>= 1)
                tmax = fmaxf(tmax, __shfl_xor_sync(0xFFFFFFFF, tmax, off));
            float m_new = fmaxf(m[rr], tmax);
            float p = __expf(s - m_new);        // -inf -> 0
            float psum = p;
            #pragma unroll
            for (int off = 16; off; off >>= 1)
                psum += __shfl_xor_sync(0xFFFFFFFF, psum, off);
            corr[rr] = __expf(m[rr] - m_new);
            l[rr] = l[rr] * corr[rr] + psum;
            m[rr] = m_new;
            pv[rr] = p;
        }
        // store P as packed row-pairs: Pd[warp][j][p] = (pv[2p], pv[2p+1])
        {
            ull p01, p23, p45, p67;
            PACK_X2(p01, pv[0], pv[1]);
            PACK_X2(p23, pv[2], pv[3]);
            PACK_X2(p45, pv[4], pv[5]);
            PACK_X2(p67, pv[6], pv[7]);
            ulonglong2* dst = (ulonglong2*)&Pd[warp * 128 + lane * 4];
            dst[0] = make_ulonglong2(p01, p23);
            dst[1] = make_ulonglong2(p45, p67);
        }
        __syncwarp();

        // phase 3: o update (row-paired f32x2); lane owns dims 4*lane..+3
        {
            ull c2[4];
            #pragma unroll
            for (int p = 0; p < 4; p++) {
                PACK_X2(c2[p], corr[2 * p], corr[2 * p + 1]);
                #pragma unroll
                for (int d = 0; d < 4; d++) MUL_X2(o2[p][d], c2[p]);
            }
        }
        #pragma unroll 8
        for (int j = 0; j < FA_BN; j++) {
            ulonglong2 pA = *(const ulonglong2*)&Pd[warp * 128 + j * 4];
            ulonglong2 pB = *(const ulonglong2*)&Pd[warp * 128 + j * 4 + 2];
            float4 v4 = *(const float4*)&Vst[j * KPAD + 4 * lane];
            ull vd[4];
            PACK_X2(vd[0], v4.x, v4.x);
            PACK_X2(vd[1], v4.y, v4.y);
            PACK_X2(vd[2], v4.z, v4.z);
            PACK_X2(vd[3], v4.w, v4.w);
            #pragma unroll
            for (int d = 0; d < 4; d++) {
                FMA_X2(o2[0][d], pA.x, vd[d]);
                FMA_X2(o2[1][d], pA.y, vd[d]);
                FMA_X2(o2[2][d], pB.x, vd[d]);
                FMA_X2(o2[3][d], pB.y, vd[d]);
            }
        }
        CP_WAIT0();
        __syncthreads();
    }

    // epilogue: unpack row-pairs, fp16 write into the wo-GEMM A operand
    #pragma unroll
    for (int p = 0; p < 4; p++) {
        float oa[4], ob[4];
        #pragma unroll
        for (int d = 0; d < 4; d++) UNPACK_X2(oa[d], ob[d], o2[p][d]);
        float inva = 1.0f / l[2 * p], invb = 1.0f / l[2 * p + 1];
        uint2 Ha, Hb;
        Ha.x = pack_h2(oa[0] * inva, oa[1] * inva);
        Ha.y = pack_h2(oa[2] * inva, oa[3] * inva);
        Hb.x = pack_h2(ob[0] * invb, ob[1] * invb);
        Hb.y = pack_h2(ob[2] * invb, ob[3] * invb);
        *(uint2*)&g_ah[((size_t)(b * T_ + r0 + 2 * p) * NH + h) * HD
                       + 4 * lane] = Ha;
        *(uint2*)&g_ah[((size_t)(b * T_ + r0 + 2 * p + 1) * NH + h) * HD
                       + 4 * lane] = Hb;
    }
}

// ---------------------------------------------------------------------------
// Launch
// ---------------------------------------------------------------------------
extern "C" void kernel_launch(void* const* d_in, const int* in_sizes, int n_in,
                              void* d_out, int out_size) {
    const float* x  = (const float*)d_in[0];
    const float* wq = (const float*)d_in[1];
    const float* wk = (const float*)d_in[2];
    const float* wv = (const float*)d_in[3];
    const float* wo = (const float*)d_in[4];
    float* out = (float*)d_out;

    float *q, *k, *v;
    cudaGetSymbolAddress((void**)&q, g_q);
    cudaGetSymbolAddress((void**)&k, g_k);
    cudaGetSymbolAddress((void**)&v, g_v);

    __half *xh, *ah, *wqh, *wql, *wkh, *wkl, *wvh, *wvl, *woh, *wol;
    cudaGetSymbolAddress((void**)&xh,  g_xh);
    cudaGetSymbolAddress((void**)&ah,  g_ah);
    cudaGetSymbolAddress((void**)&wqh, g_wqh); cudaGetSymbolAddress((void**)&wql, g_wql);
    cudaGetSymbolAddress((void**)&wkh, g_wkh); cudaGetSymbolAddress((void**)&wkl, g_wkl);
    cudaGetSymbolAddress((void**)&wvh, g_wvh); cudaGetSymbolAddress((void**)&wvl, g_wvl);
    cudaGetSymbolAddress((void**)&woh, g_woh); cudaGetSymbolAddress((void**)&wol, g_wol);

    cudaFuncSetAttribute(fgemm2_kernel,
                         cudaFuncAttributeMaxDynamicSharedMemorySize, GEMM_SMEM);
    cudaFuncSetAttribute(flash_attn_kernel,
                         cudaFuncAttributeMaxDynamicSharedMemorySize, FLASH_SMEM);

    // 1. RoPE cache
    rope_cache_kernel<<<T_, HD>>>();

    // 2. conversions: x -> fp16; weights -> transposed fp16 hi/lo split
    {
        int n4 = (M_ * D_) / 4;
        cvt_h_kernel<<<(n4 + 255) / 256, 256>>>(x, xh, n4);
        dim3 blk(32, 8);
        cvt_splitT_kernel<<<dim3(D_ / 32, D_ / 32), blk>>>(wq, wqh, wql, D_, D_);
        cvt_splitT_kernel<<<dim3(D_ / 32, D_ / 32), blk>>>(wo, woh, wol, D_, D_);
        cvt_splitT_kernel<<<dim3(KVD / 32, D_ / 32), blk>>>(wk, wkh, wkl, D_, KVD);
        cvt_splitT_kernel<<<dim3(KVD / 32, D_ / 32), blk>>>(wv, wvh, wvl, D_, KVD);
    }

    // 3. QKV projections (fp16 2-pass tensor-core GEMM)
    {
        dim3 gq(D_ / TBN, M_ / TBM);
        fgemm2_kernel<<<gq, 256, GEMM_SMEM>>>(xh, wqh, wql, q, D_, D_);
        dim3 gkv(KVD / TBN, M_ / TBM);
        fgemm2_kernel<<<gkv, 256, GEMM_SMEM>>>(xh, wkh, wkl, k, KVD, D_);
        fgemm2_kernel<<<gkv, 256, GEMM_SMEM>>>(xh, wvh, wvl, v, KVD, D_);
    }

    // 4. RoPE on q and k
    {
        int nq = M_ * NH * 64;
        rope_apply_kernel<<<(nq + 255) / 256, 256>>>(q, NH);
        int nk = M_ * NKV * 64;
        rope_apply_kernel<<<(nk + 255) / 256, 256>>>(k, NKV);
    }

    // 5. Causal GQA attention (writes fp16 g_ah directly)
    {
        dim3 g(T_ / FA_QROWS, B_ * NKV);
        flash_attn_kernel<<<g, 512, FLASH_SMEM>>>();
    }

    // 6. Output projection -> d_out
    {
        dim3 go(D_ / TBN, M_ / TBM);
        fgemm2_kernel<<<go, 256, GEMM_SMEM>>>(ah, woh, wol, out, D_, D_);
    }
}